// round 7
// baseline (speedup 1.0000x reference)
#include <cuda_runtime.h>
#include <cuda_bf16.h>
#include <math.h>

// ---------------- problem constants ----------------
#define EMB    300
#define SEQ    100
#define KW     5
#define KN     50
#define KMAX   3
#define MLP1   75
#define LP     (SEQ - KW + 1)   // 96
#define EPAD   308              // smem E row pad (%4==0 for LDS.128)
#define NQ     (EMB / 4)        // 75 e-quads
#define CQ     15               // e-quads per staged chunk
#define NCH    (NQ / CQ)        // 5 chunks
#define CHFLT  (CQ * 25 * 40)   // 15000 floats per chunk (60 KB)

// ---------------- device scratch ----------------
__device__ float g_cv[EMB];
__device__ float g_gate[KN];
__device__ float g_bias[KN];
// transposed fold: g_w2[((eq*25)+(j*5+w))*40 + ng*4 + r], e=eq*4+r, n=ng*5+j
__device__ __align__(16) float g_w2[NQ * 25 * 40];

// packed fp32 FMA (sm_103a)
__device__ __forceinline__ float2 ffma2(float2 a, float2 b, float2 c) {
    float2 d;
    asm("fma.rn.f32x2 %0, %1, %2, %3;"
        : "=l"(*reinterpret_cast<unsigned long long*>(&d))
        : "l"(*reinterpret_cast<unsigned long long*>(&a)),
          "l"(*reinterpret_cast<unsigned long long*>(&b)),
          "l"(*reinterpret_cast<unsigned long long*>(&c)));
    return d;
}

// ---------------- prepA: class vector ----------------
__global__ void dazer_prepA(const int* __restrict__ q,
                            const float* __restrict__ emb) {
    int t = threadIdx.x;
    if (t < EMB) {
        float s = 0.f;
        #pragma unroll
        for (int k = 0; k < 5; k++) s += emb[(size_t)q[k] * EMB + t];
        g_cv[t] = s * 0.2f;
    }
}

// ---------------- prepB: gate+bias (blocks 0..49) and W fold (blocks 50..149)
__global__ void dazer_prepB(const float* __restrict__ conv_w,
                            const float* __restrict__ conv_b,
                            const float* __restrict__ gate_w,
                            const float* __restrict__ gate_b) {
    __shared__ float red[256];
    __shared__ float cvs[EMB];
    const int tid = threadIdx.x;
    const int bid = blockIdx.x;

    for (int e = tid; e < EMB; e += 256) cvs[e] = g_cv[e];
    __syncthreads();

    if (bid < KN) {
        const int n = bid;
        float s = 0.f;
        for (int e = tid; e < EMB; e += 256) s += cvs[e] * gate_w[e * KN + n];
        red[tid] = s; __syncthreads();
        for (int o = 128; o; o >>= 1) { if (tid < o) red[tid] += red[tid + o]; __syncthreads(); }
        if (tid == 0) g_gate[n] = 1.f / (1.f + expf(-(red[0] + gate_b[n])));
        __syncthreads();
        float bs = 0.f;
        for (int idx = tid; idx < KW * EMB; idx += 256) {
            int w = idx / EMB, e = idx - w * EMB;
            bs += cvs[e] * conv_w[(w * (3 * EMB) + 2 * EMB + e) * KN + n];
        }
        red[tid] = bs; __syncthreads();
        for (int o = 128; o; o >>= 1) { if (tid < o) red[tid] += red[tid + o]; __syncthreads(); }
        if (tid == 0) g_bias[n] = red[0] + conv_b[n];
    } else {
        // fold Weff = W1 + cv[e]*W2 - W3 into transposed layout
        const int total = KN * KW * EMB;   // 75000
        for (int idx = (bid - KN) * 256 + tid; idx < total; idx += 100 * 256) {
            int e    = idx % EMB;
            int w    = (idx / EMB) % KW;
            int n    = idx / (EMB * KW);
            int eq   = e / 4, r = e - eq * 4;
            int ng   = n / 5, j = n - ng * 5;
            int base = w * (3 * EMB);
            g_w2[(eq * 25 + j * KW + w) * 40 + ng * 4 + r] =
                  conv_w[(base + e) * KN + n]
                + cvs[e] * conv_w[(base + EMB + e) * KN + n]
                -          conv_w[(base + 2 * EMB + e) * KN + n];
        }
    }
}

// ---------------- main fused kernel: one document per CTA, 512 threads -----
// smem floats: E 30800 | Ws 15000 | convs 4800 | enc 152 | mlp1 76 | docids 100
#define SMEM_FLOATS (SEQ * EPAD + CHFLT + LP * KN + 152 + 76 + 100)

__global__ __launch_bounds__(512, 1)
void dazer_main(const int* __restrict__ input_d,
                const float* __restrict__ emb,
                const float* __restrict__ hid_w,
                const float* __restrict__ hid_b,
                const float* __restrict__ score_w,
                const float* __restrict__ score_b,
                float* __restrict__ out, int Btot) {
    extern __shared__ float sm[];
    float* E      = sm;                         // [100][308]
    float* Ws     = E + SEQ * EPAD;             // [15][25][10][4] chunk
    float* convs  = Ws + CHFLT;                 // [96][50]
    float* enc    = convs + LP * KN;            // [152]
    float* mlp1s  = enc + 152;                  // [76]
    int*   docids = (int*)(mlp1s + 76);         // [100]

    const int tid = threadIdx.x;
    const int b   = blockIdx.x;

    if (tid < SEQ) docids[tid] = input_d[b * SEQ + tid];
    __syncthreads();

    // gather embeddings via float4 (emb rows are 1200B = 16B-aligned)
    {
        float4* E4p = (float4*)E;  // careful: rows padded, write per-row
        for (int q4 = tid; q4 < SEQ * (EMB / 4); q4 += 512) {
            int s  = q4 / (EMB / 4);
            int e4 = q4 - s * (EMB / 4);
            const float4* src = (const float4*)(emb + (size_t)docids[s] * EMB);
            *(float4*)&E[s * EPAD + e4 * 4] = src[e4];
        }
        (void)E4p;
    }

    // thread tile: 2 t-rows x 5 filters; 480 real tiles, rest are dummies
    int tg = tid / 10;          // 0..51
    int ng = tid - tg * 10;     // 0..9
    const bool real = (tid < 480);
    if (!real) { tg = 47; ng = 9; }
    const int t0 = tg * 2;      // 0..94
    const int n0 = ng * 5;

    float2 acc[2][5];
    #pragma unroll
    for (int k = 0; k < 2; k++)
        #pragma unroll
        for (int j = 0; j < 5; j++) acc[k][j] = make_float2(0.f, 0.f);

    const float4* __restrict__ Wsrc = (const float4*)g_w2;
    float4* Ws4 = (float4*)Ws;

    #pragma unroll 1
    for (int c = 0; c < NCH; c++) {
        __syncthreads();   // previous chunk consumed (covers E-gather on c==0)
        // stage 60KB W chunk (coalesced float4 copy)
        {
            const float4* src = Wsrc + c * (CHFLT / 4);
            #pragma unroll
            for (int i = 0; i < 8; i++) {
                int idx = i * 512 + tid;
                if (idx < CHFLT / 4) Ws4[idx] = src[idx];
            }
        }
        __syncthreads();

        #pragma unroll 1
        for (int eql = 0; eql < CQ; eql++) {
            const int ecol = (c * CQ + eql) * 4;
            // E rows t0..t0+5, this e-quad
            float4 E4[6];
            #pragma unroll
            for (int k = 0; k < 6; k++)
                E4[k] = *(const float4*)&E[(t0 + k) * EPAD + ecol];

            const float4* Wq = Ws4 + eql * 250;   // [j][w][ng]
            #pragma unroll
            for (int j = 0; j < 5; j++) {
                #pragma unroll
                for (int w = 0; w < 5; w++) {
                    // warp reads 10 consecutive float4s -> 2 wavefronts, 0 conflicts
                    float4 w4 = Wq[(j * KW + w) * 10 + ng];
                    float2 wlo = make_float2(w4.x, w4.y);
                    float2 whi = make_float2(w4.z, w4.w);
                    #pragma unroll
                    for (int k = 0; k < 2; k++) {
                        float2 elo = make_float2(E4[w + k].x, E4[w + k].y);
                        float2 ehi = make_float2(E4[w + k].z, E4[w + k].w);
                        acc[k][j] = ffma2(elo, wlo, acc[k][j]);
                        acc[k][j] = ffma2(ehi, whi, acc[k][j]);
                    }
                }
            }
        }
    }

    // gate + bias, write conv outputs to smem
    if (real) {
        #pragma unroll
        for (int j = 0; j < 5; j++) {
            int n = n0 + j;
            float gg = g_gate[n], bb = g_bias[n];
            #pragma unroll
            for (int k = 0; k < 2; k++)
                convs[(t0 + k) * KN + n] = gg * ((acc[k][j].x + acc[k][j].y) + bb);
        }
    }
    __syncthreads();

    // top-3 (kmax) per filter, original-order (strict > == jax top_k tie-break)
    if (tid < KN) {
        const int n = tid;
        float v1 = -1e30f, v2 = -1e30f, v3 = -1e30f;
        int   i1 = 0, i2 = 0, i3 = 0;
        for (int t = 0; t < LP; t++) {
            float v = convs[t * KN + n];
            if (v > v1)      { v3 = v2; i3 = i2; v2 = v1; i2 = i1; v1 = v; i1 = t; }
            else if (v > v2) { v3 = v2; i3 = i2; v2 = v;  i2 = t; }
            else if (v > v3) { v3 = v;  i3 = t; }
        }
        float va = v1, vb = v2, vc = v3; int ia = i1, ib = i2, ic = i3;
        if (ia > ib) { float tv = va; va = vb; vb = tv; int ti = ia; ia = ib; ib = ti; }
        if (ib > ic) { float tv = vb; vb = vc; vc = tv; int ti = ib; ib = ic; ic = ti; }
        if (ia > ib) { float tv = va; va = vb; vb = tv; int ti = ia; ia = ib; ib = ti; }
        enc[n * 3 + 0] = va;
        enc[n * 3 + 1] = vb;
        enc[n * 3 + 2] = vc;
    }
    __syncthreads();

    // mlp1 = tanh(enc @ hid_w + hid_b)
    if (tid < MLP1) {
        float s = hid_b[tid];
        #pragma unroll 5
        for (int i = 0; i < KN * KMAX; i++) s += enc[i] * hid_w[i * MLP1 + tid];
        float m = tanhf(s);
        mlp1s[tid] = m;
        out[(size_t)b * MLP1 + tid] = m;
    }
    __syncthreads();

    // score = tanh(mlp1 @ score_w + score_b)
    if (tid == 0) {
        float s = score_b[0];
        for (int j = 0; j < MLP1; j++) s += mlp1s[j] * score_w[j];
        out[(size_t)Btot * MLP1 + b] = tanhf(s);
    }
}

// ---------------- launch ----------------
extern "C" void kernel_launch(void* const* d_in, const int* in_sizes, int n_in,
                              void* d_out, int out_size) {
    const int*   input_q   = (const int*)  d_in[0];
    const int*   input_d   = (const int*)  d_in[1];
    const float* emb_table = (const float*)d_in[2];
    const float* conv_w    = (const float*)d_in[3];
    const float* conv_b    = (const float*)d_in[4];
    const float* gate_w    = (const float*)d_in[5];
    const float* gate_b    = (const float*)d_in[6];
    const float* hid_w     = (const float*)d_in[7];
    const float* hid_b     = (const float*)d_in[8];
    const float* score_w   = (const float*)d_in[9];
    const float* score_b   = (const float*)d_in[10];
    float* out = (float*)d_out;

    const int Btot = in_sizes[1] / SEQ;   // 2048
    const int smem_bytes = SMEM_FLOATS * (int)sizeof(float);

    cudaFuncSetAttribute(dazer_main, cudaFuncAttributeMaxDynamicSharedMemorySize, smem_bytes);

    dazer_prepA<<<1, 320>>>(input_q, emb_table);
    dazer_prepB<<<150, 256>>>(conv_w, conv_b, gate_w, gate_b);
    dazer_main<<<Btot, 512, smem_bytes>>>(input_d, emb_table, hid_w, hid_b,
                                          score_w, score_b, out, Btot);
}

// round 8
// speedup vs baseline: 2.3420x; 2.3420x over previous
#include <cuda_runtime.h>
#include <cuda_bf16.h>
#include <math.h>

// ---------------- problem constants ----------------
#define EMB    300
#define SEQ    100
#define KW     5
#define KN     50
#define KMAX   3
#define MLP1   75
#define LP     (SEQ - KW + 1)   // 96
#define NQ     (EMB / 4)        // 75 e-quads
#define CQ     15               // e-quads per staged chunk
#define CE     (CQ * 4)         // 60 e per chunk
#define NCH    (NQ / CQ)        // 5 chunks
#define CHFLT  (CQ * 25 * 40)   // 15000 floats per W chunk (60 KB)
#define EPAD2  64               // E chunk row pad (floats)
#define TT     8                // t-rows per thread
#define TN     5                // filters per thread

// ---------------- device scratch ----------------
__device__ float g_cv[EMB];
__device__ float g_gate[KN];
__device__ float g_bias[KN];
// transposed fold: g_w2[(eq*25 + j*5 + w)*40 + ng*4 + r], e=eq*4+r, n=ng*5+j
__device__ __align__(16) float g_w2[NQ * 25 * 40];

// packed fp32 FMA (sm_103a)
__device__ __forceinline__ float2 ffma2(float2 a, float2 b, float2 c) {
    float2 d;
    asm("fma.rn.f32x2 %0, %1, %2, %3;"
        : "=l"(*reinterpret_cast<unsigned long long*>(&d))
        : "l"(*reinterpret_cast<unsigned long long*>(&a)),
          "l"(*reinterpret_cast<unsigned long long*>(&b)),
          "l"(*reinterpret_cast<unsigned long long*>(&c)));
    return d;
}

// ---------------- prepA: class vector ----------------
__global__ void dazer_prepA(const int* __restrict__ q,
                            const float* __restrict__ emb) {
    int t = threadIdx.x;
    if (t < EMB) {
        float s = 0.f;
        #pragma unroll
        for (int k = 0; k < 5; k++) s += emb[(size_t)q[k] * EMB + t];
        g_cv[t] = s * 0.2f;
    }
}

// ---------------- prepB: gate+bias (blocks 0..49) and W fold (blocks 50..149)
__global__ void dazer_prepB(const float* __restrict__ conv_w,
                            const float* __restrict__ conv_b,
                            const float* __restrict__ gate_w,
                            const float* __restrict__ gate_b) {
    __shared__ float red[256];
    __shared__ float cvs[EMB];
    const int tid = threadIdx.x;
    const int bid = blockIdx.x;

    for (int e = tid; e < EMB; e += 256) cvs[e] = g_cv[e];
    __syncthreads();

    if (bid < KN) {
        const int n = bid;
        float s = 0.f;
        for (int e = tid; e < EMB; e += 256) s += cvs[e] * gate_w[e * KN + n];
        red[tid] = s; __syncthreads();
        for (int o = 128; o; o >>= 1) { if (tid < o) red[tid] += red[tid + o]; __syncthreads(); }
        if (tid == 0) g_gate[n] = 1.f / (1.f + expf(-(red[0] + gate_b[n])));
        __syncthreads();
        float bs = 0.f;
        for (int idx = tid; idx < KW * EMB; idx += 256) {
            int w = idx / EMB, e = idx - w * EMB;
            bs += cvs[e] * conv_w[(w * (3 * EMB) + 2 * EMB + e) * KN + n];
        }
        red[tid] = bs; __syncthreads();
        for (int o = 128; o; o >>= 1) { if (tid < o) red[tid] += red[tid + o]; __syncthreads(); }
        if (tid == 0) g_bias[n] = red[0] + conv_b[n];
    } else {
        // fold Weff = W1 + cv[e]*W2 - W3 into transposed layout
        const int total = KN * KW * EMB;   // 75000
        for (int idx = (bid - KN) * 256 + tid; idx < total; idx += 100 * 256) {
            int e    = idx % EMB;
            int w    = (idx / EMB) % KW;
            int n    = idx / (EMB * KW);
            int eq   = e / 4, r = e - eq * 4;
            int ng   = n / 5, j = n - ng * 5;
            int base = w * (3 * EMB);
            g_w2[(eq * 25 + j * KW + w) * 40 + ng * 4 + r] =
                  conv_w[(base + e) * KN + n]
                + cvs[e] * conv_w[(base + EMB + e) * KN + n]
                -          conv_w[(base + 2 * EMB + e) * KN + n];
        }
    }
}

// ---------------- main fused kernel: 1 doc/CTA, 128 threads, 2 CTAs/SM -----
// smem floats: E 100*64=6400 | Ws 15000 | convs 4800 | enc 152 | mlp1 76 | docids 100
#define SMEM_FLOATS (SEQ * EPAD2 + CHFLT + LP * KN + 152 + 76 + 100)

__global__ __launch_bounds__(128, 2)
void dazer_main(const int* __restrict__ input_d,
                const float* __restrict__ emb,
                const float* __restrict__ hid_w,
                const float* __restrict__ hid_b,
                const float* __restrict__ score_w,
                const float* __restrict__ score_b,
                float* __restrict__ out, int Btot) {
    extern __shared__ float sm[];
    float* E      = sm;                         // [100][64] e-chunk
    float* Ws     = E + SEQ * EPAD2;            // [15][25][10][4] W chunk
    float* convs  = Ws + CHFLT;                 // [96][50]
    float* enc    = convs + LP * KN;            // [152]
    float* mlp1s  = enc + 152;                  // [76]
    int*   docids = (int*)(mlp1s + 76);         // [100]

    const int tid = threadIdx.x;
    const int b   = blockIdx.x;

    if (tid < SEQ) docids[tid] = input_d[b * SEQ + tid];
    __syncthreads();

    // thread tile: 8 t-rows x 5 filters; 120 real tiles, 8 dummies
    int tg = tid / 10;          // 0..12
    int ng = tid - tg * 10;     // 0..9
    const bool real = (tid < 120);
    if (!real) { tg = 11; ng = 9; }
    const int t0 = tg * TT;     // 0..88
    const int n0 = ng * TN;

    float2 acc[TT][TN];
    #pragma unroll
    for (int k = 0; k < TT; k++)
        #pragma unroll
        for (int j = 0; j < TN; j++) acc[k][j] = make_float2(0.f, 0.f);

    const float4* __restrict__ Wsrc = (const float4*)g_w2;
    float4* Ws4 = (float4*)Ws;

    #pragma unroll 1
    for (int c = 0; c < NCH; c++) {
        __syncthreads();   // previous chunk fully consumed
        // stage W chunk (coalesced float4): 3750 float4
        {
            const float4* src = Wsrc + c * (CHFLT / 4);
            #pragma unroll
            for (int i = 0; i < 30; i++) {
                int idx = i * 128 + tid;
                if (idx < CHFLT / 4) Ws4[idx] = src[idx];
            }
        }
        // stage E chunk: rows 0..99, e-cols [c*60, c*60+60) -> 1500 float4
        {
            #pragma unroll
            for (int i = 0; i < 12; i++) {
                int idx = i * 128 + tid;
                if (idx < SEQ * (CE / 4)) {
                    int row = idx / (CE / 4);
                    int c4  = idx - row * (CE / 4);
                    *(float4*)&E[row * EPAD2 + c4 * 4] =
                        *(const float4*)(emb + (size_t)docids[row] * EMB + c * CE + c4 * 4);
                }
            }
        }
        __syncthreads();

        #pragma unroll 1
        for (int eql = 0; eql < CQ; eql++) {
            float4 E4[TT + 4];
            #pragma unroll
            for (int k = 0; k < TT + 4; k++)
                E4[k] = *(const float4*)&E[(t0 + k) * EPAD2 + eql * 4];

            const float4* Wq = Ws4 + eql * 250;   // [j][w][ng][4floats]
            #pragma unroll
            for (int j = 0; j < TN; j++) {
                #pragma unroll
                for (int w = 0; w < KW; w++) {
                    // warp reads 10 consecutive float4 -> 2 wavefronts
                    float4 w4 = Wq[(j * KW + w) * 10 + ng];
                    float2 wlo = make_float2(w4.x, w4.y);
                    float2 whi = make_float2(w4.z, w4.w);
                    #pragma unroll
                    for (int k = 0; k < TT; k++) {
                        float2 elo = make_float2(E4[w + k].x, E4[w + k].y);
                        float2 ehi = make_float2(E4[w + k].z, E4[w + k].w);
                        acc[k][j] = ffma2(elo, wlo, acc[k][j]);
                        acc[k][j] = ffma2(ehi, whi, acc[k][j]);
                    }
                }
            }
        }
    }

    // gate + bias, write conv outputs to smem
    if (real) {
        #pragma unroll
        for (int j = 0; j < TN; j++) {
            int n = n0 + j;
            float gg = g_gate[n], bb = g_bias[n];
            #pragma unroll
            for (int k = 0; k < TT; k++)
                convs[(t0 + k) * KN + n] = gg * ((acc[k][j].x + acc[k][j].y) + bb);
        }
    }
    __syncthreads();

    // top-3 (kmax) per filter, original-order (strict > == jax top_k tie-break)
    if (tid < KN) {
        const int n = tid;
        float v1 = -1e30f, v2 = -1e30f, v3 = -1e30f;
        int   i1 = 0, i2 = 0, i3 = 0;
        for (int t = 0; t < LP; t++) {
            float v = convs[t * KN + n];
            if (v > v1)      { v3 = v2; i3 = i2; v2 = v1; i2 = i1; v1 = v; i1 = t; }
            else if (v > v2) { v3 = v2; i3 = i2; v2 = v;  i2 = t; }
            else if (v > v3) { v3 = v;  i3 = t; }
        }
        float va = v1, vb = v2, vc = v3; int ia = i1, ib = i2, ic = i3;
        if (ia > ib) { float tv = va; va = vb; vb = tv; int ti = ia; ia = ib; ib = ti; }
        if (ib > ic) { float tv = vb; vb = vc; vc = tv; int ti = ib; ib = ic; ic = ti; }
        if (ia > ib) { float tv = va; va = vb; vb = tv; int ti = ia; ia = ib; ib = ti; }
        enc[n * 3 + 0] = va;
        enc[n * 3 + 1] = vb;
        enc[n * 3 + 2] = vc;
    }
    __syncthreads();

    // mlp1 = tanh(enc @ hid_w + hid_b)
    if (tid < MLP1) {
        float s = hid_b[tid];
        #pragma unroll 5
        for (int i = 0; i < KN * KMAX; i++) s += enc[i] * hid_w[i * MLP1 + tid];
        float m = tanhf(s);
        mlp1s[tid] = m;
        out[(size_t)b * MLP1 + tid] = m;
    }
    __syncthreads();

    // score = tanh(mlp1 @ score_w + score_b)
    if (tid == 0) {
        float s = score_b[0];
        for (int j = 0; j < MLP1; j++) s += mlp1s[j] * score_w[j];
        out[(size_t)Btot * MLP1 + b] = tanhf(s);
    }
}

// ---------------- launch ----------------
extern "C" void kernel_launch(void* const* d_in, const int* in_sizes, int n_in,
                              void* d_out, int out_size) {
    const int*   input_q   = (const int*)  d_in[0];
    const int*   input_d   = (const int*)  d_in[1];
    const float* emb_table = (const float*)d_in[2];
    const float* conv_w    = (const float*)d_in[3];
    const float* conv_b    = (const float*)d_in[4];
    const float* gate_w    = (const float*)d_in[5];
    const float* gate_b    = (const float*)d_in[6];
    const float* hid_w     = (const float*)d_in[7];
    const float* hid_b     = (const float*)d_in[8];
    const float* score_w   = (const float*)d_in[9];
    const float* score_b   = (const float*)d_in[10];
    float* out = (float*)d_out;

    const int Btot = in_sizes[1] / SEQ;   // 2048
    const int smem_bytes = SMEM_FLOATS * (int)sizeof(float);

    cudaFuncSetAttribute(dazer_main, cudaFuncAttributeMaxDynamicSharedMemorySize, smem_bytes);

    dazer_prepA<<<1, 320>>>(input_q, emb_table);
    dazer_prepB<<<150, 256>>>(conv_w, conv_b, gate_w, gate_b);
    dazer_main<<<Btot, 128, smem_bytes>>>(input_d, emb_table, hid_w, hid_b,
                                          score_w, score_b, out, Btot);
}

// round 9
// speedup vs baseline: 2.5000x; 1.0675x over previous
#include <cuda_runtime.h>
#include <cuda_bf16.h>
#include <math.h>

// ---------------- problem constants ----------------
#define EMB    300
#define SEQ    100
#define KW     5
#define KN     50
#define KMAX   3
#define MLP1   75
#define LP     (SEQ - KW + 1)   // 96
#define NQ     (EMB / 4)        // 75 e-quads
#define CQ     5                // e-quads per staged chunk
#define CE     (CQ * 4)         // 20 e per chunk
#define NCH    (NQ / CQ)        // 15 chunks
#define CHFLT  (CQ * 25 * 40)   // 5000 floats per W chunk (20 KB)
#define EPAD2  36               // E chunk row stride (20 cols + 12 swizzle + pad)
#define TT     8                // t-rows per thread
#define TN     5                // filters per thread

// E row swizzle: rows 8 apart (the 4 tg-groups inside a warp) get distinct
// 16B offsets -> conflict-free LDS.128
#define SWZ(row) ((((row) >> 3) & 3) * 4)

// ---------------- device scratch ----------------
__device__ float g_cv[EMB];
__device__ float g_gate[KN];
__device__ float g_bias[KN];
// transposed fold: g_w2[(eq*25 + j*5 + w)*40 + ng*4 + r], e=eq*4+r, n=ng*5+j
__device__ __align__(16) float g_w2[NQ * 25 * 40];

// packed fp32 FMA (sm_103a)
__device__ __forceinline__ float2 ffma2(float2 a, float2 b, float2 c) {
    float2 d;
    asm("fma.rn.f32x2 %0, %1, %2, %3;"
        : "=l"(*reinterpret_cast<unsigned long long*>(&d))
        : "l"(*reinterpret_cast<unsigned long long*>(&a)),
          "l"(*reinterpret_cast<unsigned long long*>(&b)),
          "l"(*reinterpret_cast<unsigned long long*>(&c)));
    return d;
}

// ---------------- prepA: class vector ----------------
__global__ void dazer_prepA(const int* __restrict__ q,
                            const float* __restrict__ emb) {
    int t = threadIdx.x;
    if (t < EMB) {
        float s = 0.f;
        #pragma unroll
        for (int k = 0; k < 5; k++) s += emb[(size_t)q[k] * EMB + t];
        g_cv[t] = s * 0.2f;
    }
}

// ---------------- prepB: gate+bias (blocks 0..49) and W fold (blocks 50..149)
__global__ void dazer_prepB(const float* __restrict__ conv_w,
                            const float* __restrict__ conv_b,
                            const float* __restrict__ gate_w,
                            const float* __restrict__ gate_b) {
    __shared__ float red[256];
    __shared__ float cvs[EMB];
    const int tid = threadIdx.x;
    const int bid = blockIdx.x;

    for (int e = tid; e < EMB; e += 256) cvs[e] = g_cv[e];
    __syncthreads();

    if (bid < KN) {
        const int n = bid;
        float s = 0.f;
        for (int e = tid; e < EMB; e += 256) s += cvs[e] * gate_w[e * KN + n];
        red[tid] = s; __syncthreads();
        for (int o = 128; o; o >>= 1) { if (tid < o) red[tid] += red[tid + o]; __syncthreads(); }
        if (tid == 0) g_gate[n] = 1.f / (1.f + expf(-(red[0] + gate_b[n])));
        __syncthreads();
        float bs = 0.f;
        for (int idx = tid; idx < KW * EMB; idx += 256) {
            int w = idx / EMB, e = idx - w * EMB;
            bs += cvs[e] * conv_w[(w * (3 * EMB) + 2 * EMB + e) * KN + n];
        }
        red[tid] = bs; __syncthreads();
        for (int o = 128; o; o >>= 1) { if (tid < o) red[tid] += red[tid + o]; __syncthreads(); }
        if (tid == 0) g_bias[n] = red[0] + conv_b[n];
    } else {
        // fold Weff = W1 + cv[e]*W2 - W3 into transposed layout
        const int total = KN * KW * EMB;   // 75000
        for (int idx = (bid - KN) * 256 + tid; idx < total; idx += 100 * 256) {
            int e    = idx % EMB;
            int w    = (idx / EMB) % KW;
            int n    = idx / (EMB * KW);
            int eq   = e / 4, r = e - eq * 4;
            int ng   = n / 5, j = n - ng * 5;
            int base = w * (3 * EMB);
            g_w2[(eq * 25 + j * KW + w) * 40 + ng * 4 + r] =
                  conv_w[(base + e) * KN + n]
                + cvs[e] * conv_w[(base + EMB + e) * KN + n]
                -          conv_w[(base + 2 * EMB + e) * KN + n];
        }
    }
}

// ---------------- main fused kernel: 1 doc/CTA, 128 threads, 3 CTAs/SM -----
// smem floats: E 100*36=3600 | Ws 5000 | enc 152 | mlp1 76 | docids 100
// convs[4800] ALIASES [E|Ws] (epilogue only, behind a barrier)
#define SMEM_FLOATS (SEQ * EPAD2 + CHFLT + 152 + 76 + 100)

__global__ __launch_bounds__(128, 3)
void dazer_main(const int* __restrict__ input_d,
                const float* __restrict__ emb,
                const float* __restrict__ hid_w,
                const float* __restrict__ hid_b,
                const float* __restrict__ score_w,
                const float* __restrict__ score_b,
                float* __restrict__ out, int Btot) {
    extern __shared__ float sm[];
    float* E      = sm;                         // [100][36] e-chunk (swizzled)
    float* Ws     = E + SEQ * EPAD2;            // [5][25][10][4] W chunk
    float* convs  = sm;                         // [96][50] aliases E+Ws (epilogue)
    float* enc    = Ws + CHFLT;                 // [152]
    float* mlp1s  = enc + 152;                  // [76]
    int*   docids = (int*)(mlp1s + 76);         // [100]

    const int tid = threadIdx.x;
    const int b   = blockIdx.x;

    if (tid < SEQ) docids[tid] = input_d[b * SEQ + tid];
    __syncthreads();

    // thread tile: 8 t-rows x 5 filters; 120 real tiles, 8 dummies
    int tg = tid / 10;          // 0..12
    int ng = tid - tg * 10;     // 0..9
    const bool real = (tid < 120);
    if (!real) { tg = 11; ng = 9; }
    const int t0 = tg * TT;     // 0..88
    const int n0 = ng * TN;

    float2 acc[TT][TN];
    #pragma unroll
    for (int k = 0; k < TT; k++)
        #pragma unroll
        for (int j = 0; j < TN; j++) acc[k][j] = make_float2(0.f, 0.f);

    const float4* __restrict__ Wsrc = (const float4*)g_w2;
    float4* Ws4 = (float4*)Ws;

    #pragma unroll 1
    for (int c = 0; c < NCH; c++) {
        __syncthreads();   // previous chunk fully consumed
        // stage W chunk (coalesced float4): 1250 float4
        {
            const float4* src = Wsrc + c * (CHFLT / 4);
            #pragma unroll
            for (int i = 0; i < 10; i++) {
                int idx = i * 128 + tid;
                if (idx < CHFLT / 4) Ws4[idx] = src[idx];
            }
        }
        // stage E chunk: rows 0..99, e-cols [c*20, c*20+20) -> 500 float4, swizzled
        {
            #pragma unroll
            for (int i = 0; i < 4; i++) {
                int idx = i * 128 + tid;
                if (idx < SEQ * (CE / 4)) {
                    int row = idx / (CE / 4);
                    int c4  = idx - row * (CE / 4);
                    *(float4*)&E[row * EPAD2 + SWZ(row) + c4 * 4] =
                        *(const float4*)(emb + (size_t)docids[row] * EMB + c * CE + c4 * 4);
                }
            }
        }
        __syncthreads();

        #pragma unroll
        for (int eql = 0; eql < CQ; eql++) {
            float4 E4[TT + 4];
            #pragma unroll
            for (int k = 0; k < TT + 4; k++) {
                int row = t0 + k;
                E4[k] = *(const float4*)&E[row * EPAD2 + SWZ(row) + eql * 4];
            }

            const float4* Wq = Ws4 + eql * 250;   // [j][w][ng][4floats]
            #pragma unroll
            for (int j = 0; j < TN; j++) {
                #pragma unroll
                for (int w = 0; w < KW; w++) {
                    // warp reads 10 consecutive float4 -> 2 wavefronts
                    float4 w4 = Wq[(j * KW + w) * 10 + ng];
                    float2 wlo = make_float2(w4.x, w4.y);
                    float2 whi = make_float2(w4.z, w4.w);
                    #pragma unroll
                    for (int k = 0; k < TT; k++) {
                        float2 elo = make_float2(E4[w + k].x, E4[w + k].y);
                        float2 ehi = make_float2(E4[w + k].z, E4[w + k].w);
                        acc[k][j] = ffma2(elo, wlo, acc[k][j]);
                        acc[k][j] = ffma2(ehi, whi, acc[k][j]);
                    }
                }
            }
        }
    }

    __syncthreads();   // everyone done reading E/Ws before convs overwrites them

    // gate + bias, write conv outputs to smem (aliased region)
    if (real) {
        #pragma unroll
        for (int j = 0; j < TN; j++) {
            int n = n0 + j;
            float gg = g_gate[n], bb = g_bias[n];
            #pragma unroll
            for (int k = 0; k < TT; k++)
                convs[(t0 + k) * KN + n] = gg * ((acc[k][j].x + acc[k][j].y) + bb);
        }
    }
    __syncthreads();

    // top-3 (kmax) per filter, original-order (strict > == jax top_k tie-break)
    if (tid < KN) {
        const int n = tid;
        float v1 = -1e30f, v2 = -1e30f, v3 = -1e30f;
        int   i1 = 0, i2 = 0, i3 = 0;
        for (int t = 0; t < LP; t++) {
            float v = convs[t * KN + n];
            if (v > v1)      { v3 = v2; i3 = i2; v2 = v1; i2 = i1; v1 = v; i1 = t; }
            else if (v > v2) { v3 = v2; i3 = i2; v2 = v;  i2 = t; }
            else if (v > v3) { v3 = v;  i3 = t; }
        }
        float va = v1, vb = v2, vc = v3; int ia = i1, ib = i2, ic = i3;
        if (ia > ib) { float tv = va; va = vb; vb = tv; int ti = ia; ia = ib; ib = ti; }
        if (ib > ic) { float tv = vb; vb = vc; vc = tv; int ti = ib; ib = ic; ic = ti; }
        if (ia > ib) { float tv = va; va = vb; vb = tv; int ti = ia; ia = ib; ib = ti; }
        enc[n * 3 + 0] = va;
        enc[n * 3 + 1] = vb;
        enc[n * 3 + 2] = vc;
    }
    __syncthreads();

    // mlp1 = tanh(enc @ hid_w + hid_b)
    if (tid < MLP1) {
        float s = hid_b[tid];
        #pragma unroll 5
        for (int i = 0; i < KN * KMAX; i++) s += enc[i] * hid_w[i * MLP1 + tid];
        float m = tanhf(s);
        mlp1s[tid] = m;
        out[(size_t)b * MLP1 + tid] = m;
    }
    __syncthreads();

    // score = tanh(mlp1 @ score_w + score_b)
    if (tid == 0) {
        float s = score_b[0];
        for (int j = 0; j < MLP1; j++) s += mlp1s[j] * score_w[j];
        out[(size_t)Btot * MLP1 + b] = tanhf(s);
    }
}

// ---------------- launch ----------------
extern "C" void kernel_launch(void* const* d_in, const int* in_sizes, int n_in,
                              void* d_out, int out_size) {
    const int*   input_q   = (const int*)  d_in[0];
    const int*   input_d   = (const int*)  d_in[1];
    const float* emb_table = (const float*)d_in[2];
    const float* conv_w    = (const float*)d_in[3];
    const float* conv_b    = (const float*)d_in[4];
    const float* gate_w    = (const float*)d_in[5];
    const float* gate_b    = (const float*)d_in[6];
    const float* hid_w     = (const float*)d_in[7];
    const float* hid_b     = (const float*)d_in[8];
    const float* score_w   = (const float*)d_in[9];
    const float* score_b   = (const float*)d_in[10];
    float* out = (float*)d_out;

    const int Btot = in_sizes[1] / SEQ;   // 2048
    const int smem_bytes = SMEM_FLOATS * (int)sizeof(float);

    cudaFuncSetAttribute(dazer_main, cudaFuncAttributeMaxDynamicSharedMemorySize, smem_bytes);

    dazer_prepA<<<1, 320>>>(input_q, emb_table);
    dazer_prepB<<<150, 256>>>(conv_w, conv_b, gate_w, gate_b);
    dazer_main<<<Btot, 128, smem_bytes>>>(input_d, emb_table, hid_w, hid_b,
                                          score_w, score_b, out, Btot);
}

// round 12
// speedup vs baseline: 2.5307x; 1.0123x over previous
#include <cuda_runtime.h>
#include <cuda_bf16.h>
#include <math.h>
#include <stdint.h>

// ---------------- problem constants ----------------
#define EMB    300
#define SEQ    100
#define KW     5
#define KN     50
#define KMAX   3
#define MLP1   75
#define LP     (SEQ - KW + 1)   // 96
#define KC     64               // K per chunk
#define NCHK   5                // 5*64=320 >= 300 (zero pad)
#define BN     256              // B rows: n' = w*50+n (250 real, 6 pad)

// ---------------- device scratch ----------------
__device__ float g_cv[EMB];
__device__ float g_gate[KN];
__device__ float g_bias[KN];
// prefolded bf16-split B: [c][hi|lo][n' 0..255][k 0..63]
__device__ __align__(16) unsigned short g_bimg[NCHK * 2 * BN * KC];

// ---------------- helpers ----------------
__device__ __forceinline__ unsigned short f2bf(float x) {   // RN-even fp32->bf16
    unsigned u = __float_as_uint(x);
    return (unsigned short)((u + 0x7FFFu + ((u >> 16) & 1u)) >> 16);
}
__device__ __forceinline__ float bf2f(unsigned short h) {
    return __uint_as_float(((unsigned)h) << 16);
}
__device__ __forceinline__ uint32_t smem_u32(const void* p) {
    uint32_t a;
    asm("{ .reg .u64 t; cvta.to.shared.u64 t, %1; cvt.u32.u64 %0, t; }" : "=r"(a) : "l"(p));
    return a;
}
__device__ __forceinline__ void ldsm_x4(uint32_t* r, uint32_t addr) {
    asm volatile("ldmatrix.sync.aligned.m8n8.x4.shared.b16 {%0,%1,%2,%3}, [%4];"
                 : "=r"(r[0]), "=r"(r[1]), "=r"(r[2]), "=r"(r[3]) : "r"(addr));
}
__device__ __forceinline__ void mma_bf16(float* d, const uint32_t* a, const uint32_t* b) {
    asm volatile("mma.sync.aligned.m16n8k16.row.col.f32.bf16.bf16.f32 "
                 "{%0,%1,%2,%3}, {%4,%5,%6,%7}, {%8,%9}, {%0,%1,%2,%3};"
                 : "+f"(d[0]), "+f"(d[1]), "+f"(d[2]), "+f"(d[3])
                 : "r"(a[0]), "r"(a[1]), "r"(a[2]), "r"(a[3]), "r"(b[0]), "r"(b[1]));
}

// ---------------- prepA: class vector ----------------
__global__ void dazer_prepA(const int* __restrict__ q, const float* __restrict__ emb) {
    int t = threadIdx.x;
    if (t < EMB) {
        float s = 0.f;
        #pragma unroll
        for (int k = 0; k < 5; k++) s += emb[(size_t)q[k] * EMB + t];
        g_cv[t] = s * 0.2f;
    }
}

// ---------------- prepB: gate+bias (blk 0..49) and B fold (blk 50..149) ----
__global__ void dazer_prepB(const float* __restrict__ conv_w,
                            const float* __restrict__ conv_b,
                            const float* __restrict__ gate_w,
                            const float* __restrict__ gate_b) {
    __shared__ float red[256];
    __shared__ float cvs[EMB];
    const int tid = threadIdx.x;
    const int bid = blockIdx.x;

    for (int e = tid; e < EMB; e += 256) cvs[e] = g_cv[e];
    __syncthreads();

    if (bid < KN) {
        const int n = bid;
        float s = 0.f;
        for (int e = tid; e < EMB; e += 256) s += cvs[e] * gate_w[e * KN + n];
        red[tid] = s; __syncthreads();
        for (int o = 128; o; o >>= 1) { if (tid < o) red[tid] += red[tid + o]; __syncthreads(); }
        if (tid == 0) g_gate[n] = 1.f / (1.f + expf(-(red[0] + gate_b[n])));
        __syncthreads();
        float bs = 0.f;
        for (int idx = tid; idx < KW * EMB; idx += 256) {
            int w = idx / EMB, e = idx - w * EMB;
            bs += cvs[e] * conv_w[(w * (3 * EMB) + 2 * EMB + e) * KN + n];
        }
        red[tid] = bs; __syncthreads();
        for (int o = 128; o; o >>= 1) { if (tid < o) red[tid] += red[tid + o]; __syncthreads(); }
        if (tid == 0) g_bias[n] = red[0] + conv_b[n];
    } else {
        // fold Weff = W1 + cv[e]*W2 - W3 -> bf16 hi/lo, row n' = w*50+n
        const int total = NCHK * BN * KC;   // 81920
        for (int idx = (bid - KN) * 256 + tid; idx < total; idx += 100 * 256) {
            int k = idx & 63;
            int r = (idx >> 6) & (BN - 1);
            int c = idx >> 14;
            float v = 0.f;
            if (r < KW * KN) {
                int w = r / KN, n = r - w * KN;
                int e = c * KC + k;
                if (e < EMB) {
                    int base = w * (3 * EMB);
                    v = conv_w[(base + e) * KN + n]
                      + cvs[e] * conv_w[(base + EMB + e) * KN + n]
                      -          conv_w[(base + 2 * EMB + e) * KN + n];
                }
            }
            unsigned short hi = f2bf(v);
            unsigned short lo = f2bf(v - bf2f(hi));
            g_bimg[((c * 2 + 0) * BN + r) * KC + k] = hi;
            g_bimg[((c * 2 + 1) * BN + r) * KC + k] = lo;
        }
    }
}

// ---------------- main kernel: 1 doc/CTA, 256 thr, HMMA bf16 split ---------
// byte layout in dynamic smem:
#define ES_HI   2048
#define ES_LO   (ES_HI + 128 * 144)      // 20480
#define BS_HI   (ES_LO + 128 * 144)      // 38912
#define BS_LO   (BS_HI + BN * 144)       // 75776
#define DSM_OFF (BS_LO + BN * 144)       // 112640
#define DSTRIDE 264                      // floats per Dsm row
#define SMEM_BYTES (DSM_OFF + SEQ * DSTRIDE * 4)   // 218240

__global__ __launch_bounds__(256, 1)
void dazer_main(const int* __restrict__ input_d,
                const float* __restrict__ emb,
                const float* __restrict__ hid_w,
                const float* __restrict__ hid_b,
                const float* __restrict__ score_w,
                const float* __restrict__ score_b,
                float* __restrict__ out, int Btot) {
    extern __shared__ char smc[];
    int*   docids = (int*)smc;                    // [104]
    float* enc    = (float*)(smc + 448);          // [152]
    float* mlp1s  = (float*)(smc + 1088);         // [76]
    float* Dsm    = (float*)(smc + DSM_OFF);      // [100][264]
    float* convs  = (float*)(smc + ES_HI);        // [96*50] aliases staging (epilogue)

    const int tid  = threadIdx.x;
    const int lane = tid & 31;
    const int wid  = tid >> 5;
    const int b    = blockIdx.x;

    if (tid < SEQ) docids[tid] = input_d[b * SEQ + tid];

    // per-lane ldmatrix base offsets
    const uint32_t sb = smem_u32(smc);
    const int m0 = wid * 16;
    const uint32_t aHi = sb + ES_HI + (uint32_t)(m0 + (lane & 15)) * 144 + ((lane >> 4) * 16);
    const uint32_t aLo = aHi + (ES_LO - ES_HI);
    const uint32_t brow = (uint32_t)((lane & 7) + ((lane & 16) >> 1));
    const uint32_t bHi = sb + BS_HI + brow * 144 + ((lane & 8) << 1);
    const uint32_t bLo = bHi + (BS_LO - BS_HI);

    float acc[128];
    #pragma unroll
    for (int i = 0; i < 128; i++) acc[i] = 0.f;

    #pragma unroll 1
    for (int c = 0; c < NCHK; c++) {
        __syncthreads();   // previous chunk's tiles consumed (and docids ready on c==0)

        // ---- stage E chunk (hi/lo bf16), rows 0..127 (>=100 zero), k pad zero
        #pragma unroll
        for (int i = 0; i < 16; i++) {             // 128 rows * 32 kp / 256 thr
            int idx = i * 256 + tid;
            int row = idx >> 5;
            int kp  = idx & 31;
            int e0  = c * KC + kp * 2;
            float v0 = 0.f, v1 = 0.f;
            if (row < SEQ) {
                const float* er = emb + (size_t)docids[row] * EMB;
                if (e0 < EMB)     v0 = er[e0];
                if (e0 + 1 < EMB) v1 = er[e0 + 1];
            }
            unsigned short h0 = f2bf(v0), h1 = f2bf(v1);
            unsigned short l0 = f2bf(v0 - bf2f(h0)), l1 = f2bf(v1 - bf2f(h1));
            *(uint32_t*)(smc + ES_HI + row * 144 + kp * 4) = (uint32_t)h0 | ((uint32_t)h1 << 16);
            *(uint32_t*)(smc + ES_LO + row * 144 + kp * 4) = (uint32_t)l0 | ((uint32_t)l1 << 16);
        }
        // ---- stage B chunk (hi/lo), 256 rows x 128B -> 144B stride
        {
            const char* bsrc = (const char*)g_bimg;
            #pragma unroll
            for (int img = 0; img < 2; img++) {
                int dsto = img ? BS_LO : BS_HI;
                #pragma unroll
                for (int i = 0; i < 8; i++) {      // 256 rows * 8 u16B / 256 thr
                    int idx = i * 256 + tid;
                    int row = idx >> 3, u = idx & 7;
                    *(float4*)(smc + dsto + row * 144 + u * 16) =
                        *(const float4*)(bsrc + ((size_t)((c * 2 + img) * BN + row) * KC) * 2 + u * 16);
                }
            }
        }
        __syncthreads();

        // ---- warp GEMM: D[16, 256] += E[16, 64] * B[256, 64]^T (3 split terms)
        #pragma unroll
        for (int ks = 0; ks < 4; ks++) {
            uint32_t ah[4], al[4];
            ldsm_x4(ah, aHi + ks * 32);
            ldsm_x4(al, aLo + ks * 32);
            #pragma unroll
            for (int jp = 0; jp < 16; jp++) {      // FIX: 16 jp-pairs = 256 n-cols (was 8)
                uint32_t bb = (uint32_t)(jp * 16 * 144 + ks * 32);
                uint32_t bh[4], bl[4];
                ldsm_x4(bh, bHi + bb);
                mma_bf16(acc + (2 * jp) * 4,     ah, bh);
                mma_bf16(acc + (2 * jp + 1) * 4, ah, bh + 2);
                mma_bf16(acc + (2 * jp) * 4,     al, bh);
                mma_bf16(acc + (2 * jp + 1) * 4, al, bh + 2);
                ldsm_x4(bl, bLo + bb);
                mma_bf16(acc + (2 * jp) * 4,     ah, bl);
                mma_bf16(acc + (2 * jp + 1) * 4, ah, bl + 2);
            }
        }
    }

    // ---- dump fragments to Dsm (rows < 100 only)
    {
        int r0 = m0 + (lane >> 2);
        int cb = (lane & 3) * 2;
        #pragma unroll
        for (int j = 0; j < 32; j++) {
            int col = j * 8 + cb;
            if (r0 < SEQ) {
                Dsm[r0 * DSTRIDE + col]     = acc[j * 4 + 0];
                Dsm[r0 * DSTRIDE + col + 1] = acc[j * 4 + 1];
            }
            if (r0 + 8 < SEQ) {
                Dsm[(r0 + 8) * DSTRIDE + col]     = acc[j * 4 + 2];
                Dsm[(r0 + 8) * DSTRIDE + col + 1] = acc[j * 4 + 3];
            }
        }
    }
    __syncthreads();   // all mma/ldmatrix done -> safe to overwrite staging with convs

    // ---- conv[t,n] = gate[n] * (sum_w Dsm[t+w][w*50+n] + bias[n])
    for (int idx = tid; idx < LP * KN; idx += 256) {
        int t = idx / KN, n = idx - t * KN;
        float s = 0.f;
        #pragma unroll
        for (int w = 0; w < KW; w++) s += Dsm[(t + w) * DSTRIDE + w * KN + n];
        convs[idx] = g_gate[n] * (s + g_bias[n]);
    }
    __syncthreads();

    // ---- top-3 per filter, original order (strict > == jax top_k tie-break)
    if (tid < KN) {
        const int n = tid;
        float v1 = -1e30f, v2 = -1e30f, v3 = -1e30f;
        int   i1 = 0, i2 = 0, i3 = 0;
        for (int t = 0; t < LP; t++) {
            float v = convs[t * KN + n];
            if (v > v1)      { v3 = v2; i3 = i2; v2 = v1; i2 = i1; v1 = v; i1 = t; }
            else if (v > v2) { v3 = v2; i3 = i2; v2 = v;  i2 = t; }
            else if (v > v3) { v3 = v;  i3 = t; }
        }
        float va = v1, vb = v2, vc = v3; int ia = i1, ib = i2, ic = i3;
        if (ia > ib) { float tv = va; va = vb; vb = tv; int ti = ia; ia = ib; ib = ti; }
        if (ib > ic) { float tv = vb; vb = vc; vc = tv; int ti = ib; ib = ic; ic = ti; }
        if (ia > ib) { float tv = va; va = vb; vb = tv; int ti = ia; ia = ib; ib = ti; }
        enc[n * 3 + 0] = va; enc[n * 3 + 1] = vb; enc[n * 3 + 2] = vc;
    }
    __syncthreads();

    // ---- mlp1 = tanh(enc @ hid_w + hid_b)
    if (tid < MLP1) {
        float s = hid_b[tid];
        #pragma unroll 5
        for (int i = 0; i < KN * KMAX; i++) s += enc[i] * hid_w[i * MLP1 + tid];
        float m = tanhf(s);
        mlp1s[tid] = m;
        out[(size_t)b * MLP1 + tid] = m;
    }
    __syncthreads();

    // ---- score
    if (tid == 0) {
        float s = score_b[0];
        for (int j = 0; j < MLP1; j++) s += mlp1s[j] * score_w[j];
        out[(size_t)Btot * MLP1 + b] = tanhf(s);
    }
}

// ---------------- launch ----------------
extern "C" void kernel_launch(void* const* d_in, const int* in_sizes, int n_in,
                              void* d_out, int out_size) {
    const int*   input_q   = (const int*)  d_in[0];
    const int*   input_d   = (const int*)  d_in[1];
    const float* emb_table = (const float*)d_in[2];
    const float* conv_w    = (const float*)d_in[3];
    const float* conv_b    = (const float*)d_in[4];
    const float* gate_w    = (const float*)d_in[5];
    const float* gate_b    = (const float*)d_in[6];
    const float* hid_w     = (const float*)d_in[7];
    const float* hid_b     = (const float*)d_in[8];
    const float* score_w   = (const float*)d_in[9];
    const float* score_b   = (const float*)d_in[10];
    float* out = (float*)d_out;

    const int Btot = in_sizes[1] / SEQ;   // 2048

    cudaFuncSetAttribute(dazer_main, cudaFuncAttributeMaxDynamicSharedMemorySize, SMEM_BYTES);

    dazer_prepA<<<1, 320>>>(input_q, emb_table);
    dazer_prepB<<<150, 256>>>(conv_w, conv_b, gate_w, gate_b);
    dazer_main<<<Btot, 256, SMEM_BYTES>>>(input_d, emb_table, hid_w, hid_b,
                                          score_w, score_b, out, Btot);
}

// round 14
// speedup vs baseline: 2.9254x; 1.1560x over previous
#include <cuda_runtime.h>
#include <cuda_bf16.h>
#include <math.h>
#include <stdint.h>

// ---------------- problem constants ----------------
#define EMB    300
#define SEQ    100
#define KW     5
#define KN     50
#define KMAX   3
#define MLP1   75
#define LP     (SEQ - KW + 1)   // 96
#define KC     64               // K per chunk
#define NCHK   5                // 5*64=320 >= 300 (zero pad); last chunk only 3 ks
#define BN     256              // B rows: n' = w*50+n (250 real, 6 pad)

// ---------------- device scratch ----------------
__device__ float g_cv[EMB];
__device__ float g_gate[KN];
__device__ float g_bias[KN];
// prefolded bf16-split B: [c][hi|lo][n' 0..255][k 0..63]
__device__ __align__(16) unsigned short g_bimg[NCHK * 2 * BN * KC];

// ---------------- helpers ----------------
__device__ __forceinline__ unsigned short f2bf(float x) {   // RN-even fp32->bf16
    unsigned u = __float_as_uint(x);
    return (unsigned short)((u + 0x7FFFu + ((u >> 16) & 1u)) >> 16);
}
__device__ __forceinline__ float bf2f(unsigned short h) {
    return __uint_as_float(((unsigned)h) << 16);
}
__device__ __forceinline__ uint32_t smem_u32(const void* p) {
    uint32_t a;
    asm("{ .reg .u64 t; cvta.to.shared.u64 t, %1; cvt.u32.u64 %0, t; }" : "=r"(a) : "l"(p));
    return a;
}
__device__ __forceinline__ void ldsm_x4(uint32_t* r, uint32_t addr) {
    asm volatile("ldmatrix.sync.aligned.m8n8.x4.shared.b16 {%0,%1,%2,%3}, [%4];"
                 : "=r"(r[0]), "=r"(r[1]), "=r"(r[2]), "=r"(r[3]) : "r"(addr));
}
__device__ __forceinline__ void mma_bf16(float* d, const uint32_t* a, const uint32_t* b) {
    asm volatile("mma.sync.aligned.m16n8k16.row.col.f32.bf16.bf16.f32 "
                 "{%0,%1,%2,%3}, {%4,%5,%6,%7}, {%8,%9}, {%0,%1,%2,%3};"
                 : "+f"(d[0]), "+f"(d[1]), "+f"(d[2]), "+f"(d[3])
                 : "r"(a[0]), "r"(a[1]), "r"(a[2]), "r"(a[3]), "r"(b[0]), "r"(b[1]));
}

// ---------------- prepA: class vector ----------------
__global__ void dazer_prepA(const int* __restrict__ q, const float* __restrict__ emb) {
    int t = threadIdx.x;
    if (t < EMB) {
        float s = 0.f;
        #pragma unroll
        for (int k = 0; k < 5; k++) s += emb[(size_t)q[k] * EMB + t];
        g_cv[t] = s * 0.2f;
    }
}

// ---------------- prepB: gate+bias (blk 0..49) and B fold (blk 50..149) ----
__global__ void dazer_prepB(const float* __restrict__ conv_w,
                            const float* __restrict__ conv_b,
                            const float* __restrict__ gate_w,
                            const float* __restrict__ gate_b) {
    __shared__ float red[256];
    __shared__ float cvs[EMB];
    const int tid = threadIdx.x;
    const int bid = blockIdx.x;

    for (int e = tid; e < EMB; e += 256) cvs[e] = g_cv[e];
    __syncthreads();

    if (bid < KN) {
        const int n = bid;
        float s = 0.f;
        for (int e = tid; e < EMB; e += 256) s += cvs[e] * gate_w[e * KN + n];
        red[tid] = s; __syncthreads();
        for (int o = 128; o; o >>= 1) { if (tid < o) red[tid] += red[tid + o]; __syncthreads(); }
        if (tid == 0) g_gate[n] = 1.f / (1.f + expf(-(red[0] + gate_b[n])));
        __syncthreads();
        float bs = 0.f;
        for (int idx = tid; idx < KW * EMB; idx += 256) {
            int w = idx / EMB, e = idx - w * EMB;
            bs += cvs[e] * conv_w[(w * (3 * EMB) + 2 * EMB + e) * KN + n];
        }
        red[tid] = bs; __syncthreads();
        for (int o = 128; o; o >>= 1) { if (tid < o) red[tid] += red[tid + o]; __syncthreads(); }
        if (tid == 0) g_bias[n] = red[0] + conv_b[n];
    } else {
        // fold Weff = W1 + cv[e]*W2 - W3 -> bf16 hi/lo, row n' = w*50+n
        const int total = NCHK * BN * KC;   // 81920
        for (int idx = (bid - KN) * 256 + tid; idx < total; idx += 100 * 256) {
            int k = idx & 63;
            int r = (idx >> 6) & (BN - 1);
            int c = idx >> 14;
            float v = 0.f;
            if (r < KW * KN) {
                int w = r / KN, n = r - w * KN;
                int e = c * KC + k;
                if (e < EMB) {
                    int base = w * (3 * EMB);
                    v = conv_w[(base + e) * KN + n]
                      + cvs[e] * conv_w[(base + EMB + e) * KN + n]
                      -          conv_w[(base + 2 * EMB + e) * KN + n];
                }
            }
            unsigned short hi = f2bf(v);
            unsigned short lo = f2bf(v - bf2f(hi));
            g_bimg[((c * 2 + 0) * BN + r) * KC + k] = hi;
            g_bimg[((c * 2 + 1) * BN + r) * KC + k] = lo;
        }
    }
}

// ---------------- main kernel: 1 doc/CTA, 512 thr (16 warps), HMMA bf16 ----
// smem: header 2048 | staging: E_hi 2048.. , E_lo, B_hi, B_lo | Dsm ALIASES staging
#define ES_HI   2048
#define ES_LO   (ES_HI + 128 * 144)      // 20480
#define BS_HI   (ES_LO + 128 * 144)      // 38912
#define BS_LO   (BS_HI + BN * 144)       // 75776
#define STG_END (BS_LO + BN * 144)       // 112640
#define DSM_OFF 2048                     // Dsm aliases staging (post-GEMM)
#define DSTRIDE 264                      // floats per Dsm row
#define DSM_END (DSM_OFF + SEQ * DSTRIDE * 4)      // 107648
#define SMEM_BYTES (STG_END > DSM_END ? STG_END : DSM_END)   // 112640

__global__ __launch_bounds__(512, 1)
void dazer_main(const int* __restrict__ input_d,
                const float* __restrict__ emb,
                const float* __restrict__ hid_w,
                const float* __restrict__ hid_b,
                const float* __restrict__ score_w,
                const float* __restrict__ score_b,
                float* __restrict__ out, int Btot) {
    extern __shared__ char smc[];
    int*   docids = (int*)smc;                    // [104]
    float* enc    = (float*)(smc + 448);          // [152]
    float* mlp1s  = (float*)(smc + 1088);         // [76]
    float* Dsm    = (float*)(smc + DSM_OFF);      // [100][264], aliases staging

    const int tid  = threadIdx.x;
    const int lane = tid & 31;
    const int wid  = tid >> 5;        // 0..15
    const int mt   = wid >> 1;        // M-tile 0..7
    const int nh   = wid & 1;         // N-half 0..1
    const int b    = blockIdx.x;

    if (tid < SEQ) docids[tid] = input_d[b * SEQ + tid];

    // per-lane ldmatrix base offsets
    const uint32_t sb = smem_u32(smc);
    const int m0 = mt * 16;
    const uint32_t aHi = sb + ES_HI + (uint32_t)(m0 + (lane & 15)) * 144 + ((lane >> 4) * 16);
    const uint32_t aLo = aHi + (ES_LO - ES_HI);
    const uint32_t brow = (uint32_t)((lane & 7) + ((lane & 16) >> 1));
    const uint32_t bHi = sb + BS_HI + (uint32_t)(nh * 128) * 144 + brow * 144 + ((lane & 8) << 1);
    const uint32_t bLo = bHi + (BS_LO - BS_HI);

    float acc[64];
    #pragma unroll
    for (int i = 0; i < 64; i++) acc[i] = 0.f;

    #pragma unroll 1
    for (int c = 0; c < NCHK; c++) {
        __syncthreads();   // previous chunk's tiles consumed (docids ready on c==0)

        // ---- stage E chunk (hi/lo bf16), rows 0..127, k pad zero
        #pragma unroll
        for (int i = 0; i < 8; i++) {              // 128 rows * 32 kp / 512 thr
            int idx = i * 512 + tid;
            int row = idx >> 5;
            int kp  = idx & 31;
            int e0  = c * KC + kp * 2;
            float v0 = 0.f, v1 = 0.f;
            if (row < SEQ) {
                const float* er = emb + (size_t)docids[row] * EMB;
                if (e0 < EMB)     v0 = er[e0];
                if (e0 + 1 < EMB) v1 = er[e0 + 1];
            }
            unsigned short h0 = f2bf(v0), h1 = f2bf(v1);
            unsigned short l0 = f2bf(v0 - bf2f(h0)), l1 = f2bf(v1 - bf2f(h1));
            *(uint32_t*)(smc + ES_HI + row * 144 + kp * 4) = (uint32_t)h0 | ((uint32_t)h1 << 16);
            *(uint32_t*)(smc + ES_LO + row * 144 + kp * 4) = (uint32_t)l0 | ((uint32_t)l1 << 16);
        }
        // ---- stage B chunk (hi/lo), 256 rows x 128B -> 144B stride
        {
            const char* bsrc = (const char*)g_bimg;
            #pragma unroll
            for (int img = 0; img < 2; img++) {
                int dsto = img ? BS_LO : BS_HI;
                #pragma unroll
                for (int i = 0; i < 4; i++) {      // 256 rows * 8 u16B / 512 thr
                    int idx = i * 512 + tid;
                    int row = idx >> 3, u = idx & 7;
                    *(float4*)(smc + dsto + row * 144 + u * 16) =
                        *(const float4*)(bsrc + ((size_t)((c * 2 + img) * BN + row) * KC) * 2 + u * 16);
                }
            }
        }
        __syncthreads();

        // ---- warp GEMM: D[16, 128] += E[16,64] * B[128,64]^T, 3 split terms
        // K-trim: last chunk's ks=3 covers e>=304 (all zero) -> skip
        const int ksmax = (c == NCHK - 1) ? 3 : 4;
        #pragma unroll
        for (int ks = 0; ks < 4; ks++) {
            if (ks >= ksmax) break;
            uint32_t ah[4], al[4];
            ldsm_x4(ah, aHi + ks * 32);
            ldsm_x4(al, aLo + ks * 32);
            #pragma unroll
            for (int jp = 0; jp < 8; jp++) {       // 8 jp-pairs = 128 n-cols (this half)
                uint32_t bb = (uint32_t)(jp * 16 * 144 + ks * 32);
                uint32_t bh[4], bl[4];
                ldsm_x4(bh, bHi + bb);
                mma_bf16(acc + (2 * jp) * 4,     ah, bh);
                mma_bf16(acc + (2 * jp + 1) * 4, ah, bh + 2);
                mma_bf16(acc + (2 * jp) * 4,     al, bh);
                mma_bf16(acc + (2 * jp + 1) * 4, al, bh + 2);
                ldsm_x4(bl, bLo + bb);
                mma_bf16(acc + (2 * jp) * 4,     ah, bl);
                mma_bf16(acc + (2 * jp + 1) * 4, ah, bl + 2);
            }
        }
    }

    __syncthreads();   // all mma/ldsm done -> staging dead -> Dsm may overwrite it

    // ---- dump fragments to Dsm (rows < 100 only)
    {
        int r0 = m0 + (lane >> 2);
        int cb = (lane & 3) * 2;
        #pragma unroll
        for (int j = 0; j < 16; j++) {
            int col = nh * 128 + j * 8 + cb;
            if (r0 < SEQ) {
                Dsm[r0 * DSTRIDE + col]     = acc[j * 4 + 0];
                Dsm[r0 * DSTRIDE + col + 1] = acc[j * 4 + 1];
            }
            if (r0 + 8 < SEQ) {
                Dsm[(r0 + 8) * DSTRIDE + col]     = acc[j * 4 + 2];
                Dsm[(r0 + 8) * DSTRIDE + col + 1] = acc[j * 4 + 3];
            }
        }
    }
    __syncthreads();

    // ---- top-3 per filter with on-the-fly conv (order: w ascending, == R12)
    if (tid < KN) {
        const int n = tid;
        const float gg = g_gate[n], bb = g_bias[n];
        float v1 = -1e30f, v2 = -1e30f, v3 = -1e30f;
        int   i1 = 0, i2 = 0, i3 = 0;
        for (int t = 0; t < LP; t++) {
            float s = 0.f;
            #pragma unroll
            for (int w = 0; w < KW; w++) s += Dsm[(t + w) * DSTRIDE + w * KN + n];
            float v = gg * (s + bb);
            if (v > v1)      { v3 = v2; i3 = i2; v2 = v1; i2 = i1; v1 = v; i1 = t; }
            else if (v > v2) { v3 = v2; i3 = i2; v2 = v;  i2 = t; }
            else if (v > v3) { v3 = v;  i3 = t; }
        }
        float va = v1, vb = v2, vc = v3; int ia = i1, ib = i2, ic = i3;
        if (ia > ib) { float tv = va; va = vb; vb = tv; int ti = ia; ia = ib; ib = ti; }
        if (ib > ic) { float tv = vb; vb = vc; vc = tv; int ti = ib; ib = ic; ic = ti; }
        if (ia > ib) { float tv = va; va = vb; vb = tv; int ti = ia; ia = ib; ib = ti; }
        enc[n * 3 + 0] = va; enc[n * 3 + 1] = vb; enc[n * 3 + 2] = vc;
    }
    __syncthreads();

    // ---- mlp1 = tanh(enc @ hid_w + hid_b)
    if (tid < MLP1) {
        float s = hid_b[tid];
        #pragma unroll 5
        for (int i = 0; i < KN * KMAX; i++) s += enc[i] * hid_w[i * MLP1 + tid];
        float m = tanhf(s);
        mlp1s[tid] = m;
        out[(size_t)b * MLP1 + tid] = m;
    }
    __syncthreads();

    // ---- score
    if (tid == 0) {
        float s = score_b[0];
        for (int j = 0; j < MLP1; j++) s += mlp1s[j] * score_w[j];
        out[(size_t)Btot * MLP1 + b] = tanhf(s);
    }
}

// ---------------- launch ----------------
extern "C" void kernel_launch(void* const* d_in, const int* in_sizes, int n_in,
                              void* d_out, int out_size) {
    const int*   input_q   = (const int*)  d_in[0];
    const int*   input_d   = (const int*)  d_in[1];
    const float* emb_table = (const float*)d_in[2];
    const float* conv_w    = (const float*)d_in[3];
    const float* conv_b    = (const float*)d_in[4];
    const float* gate_w    = (const float*)d_in[5];
    const float* gate_b    = (const float*)d_in[6];
    const float* hid_w     = (const float*)d_in[7];
    const float* hid_b     = (const float*)d_in[8];
    const float* score_w   = (const float*)d_in[9];
    const float* score_b   = (const float*)d_in[10];
    float* out = (float*)d_out;

    const int Btot = in_sizes[1] / SEQ;   // 2048

    cudaFuncSetAttribute(dazer_main, cudaFuncAttributeMaxDynamicSharedMemorySize, SMEM_BYTES);

    dazer_prepA<<<1, 320>>>(input_q, emb_table);
    dazer_prepB<<<150, 256>>>(conv_w, conv_b, gate_w, gate_b);
    dazer_main<<<Btot, 512, SMEM_BYTES>>>(input_d, emb_table, hid_w, hid_b,
                                          score_w, score_b, out, Btot);
}

// round 15
// speedup vs baseline: 3.1910x; 1.0908x over previous
#include <cuda_runtime.h>
#include <cuda_bf16.h>
#include <math.h>
#include <stdint.h>

// ---------------- problem constants ----------------
#define EMB    300
#define SEQ    100
#define KW     5
#define KN     50
#define KMAX   3
#define MLP1   75
#define LP     (SEQ - KW + 1)   // 96
#define KC     64               // K per chunk
#define NCHK   5                // 5*64=320 >= 300 (zero pad); last chunk 3 ks
#define BN     256              // B rows: n' = w*50+n (250 real, 6 pad)
#define MROWS  112              // trimmed M (7 m16 tiles cover 100 doc rows)

// ---------------- device scratch ----------------
__device__ float g_cv[EMB];
__device__ float g_gate[KN];
__device__ float g_bias[KN];
// prefolded bf16-split B: [c][hi|lo][n' 0..255][k 0..63]
__device__ __align__(16) unsigned short g_bimg[NCHK * 2 * BN * KC];

// ---------------- helpers ----------------
__device__ __forceinline__ unsigned short f2bf(float x) {   // RN-even fp32->bf16
    unsigned u = __float_as_uint(x);
    return (unsigned short)((u + 0x7FFFu + ((u >> 16) & 1u)) >> 16);
}
__device__ __forceinline__ float bf2f(unsigned short h) {
    return __uint_as_float(((unsigned)h) << 16);
}
__device__ __forceinline__ uint32_t smem_u32(const void* p) {
    uint32_t a;
    asm("{ .reg .u64 t; cvta.to.shared.u64 t, %1; cvt.u32.u64 %0, t; }" : "=r"(a) : "l"(p));
    return a;
}
__device__ __forceinline__ void ldsm_x4(uint32_t* r, uint32_t addr) {
    asm volatile("ldmatrix.sync.aligned.m8n8.x4.shared.b16 {%0,%1,%2,%3}, [%4];"
                 : "=r"(r[0]), "=r"(r[1]), "=r"(r[2]), "=r"(r[3]) : "r"(addr));
}
__device__ __forceinline__ void mma_bf16(float* d, const uint32_t* a, const uint32_t* b) {
    asm volatile("mma.sync.aligned.m16n8k16.row.col.f32.bf16.bf16.f32 "
                 "{%0,%1,%2,%3}, {%4,%5,%6,%7}, {%8,%9}, {%0,%1,%2,%3};"
                 : "+f"(d[0]), "+f"(d[1]), "+f"(d[2]), "+f"(d[3])
                 : "r"(a[0]), "r"(a[1]), "r"(a[2]), "r"(a[3]), "r"(b[0]), "r"(b[1]));
}

// ---------------- prepA: class vector ----------------
__global__ void dazer_prepA(const int* __restrict__ q, const float* __restrict__ emb) {
    int t = threadIdx.x;
    if (t < EMB) {
        float s = 0.f;
        #pragma unroll
        for (int k = 0; k < 5; k++) s += emb[(size_t)q[k] * EMB + t];
        g_cv[t] = s * 0.2f;
    }
}

// ---------------- prepB: gate+bias (blk 0..49) and B fold (blk 50..149) ----
__global__ void dazer_prepB(const float* __restrict__ conv_w,
                            const float* __restrict__ conv_b,
                            const float* __restrict__ gate_w,
                            const float* __restrict__ gate_b) {
    __shared__ float red[256];
    __shared__ float cvs[EMB];
    const int tid = threadIdx.x;
    const int bid = blockIdx.x;

    for (int e = tid; e < EMB; e += 256) cvs[e] = g_cv[e];
    __syncthreads();

    if (bid < KN) {
        const int n = bid;
        float s = 0.f;
        for (int e = tid; e < EMB; e += 256) s += cvs[e] * gate_w[e * KN + n];
        red[tid] = s; __syncthreads();
        for (int o = 128; o; o >>= 1) { if (tid < o) red[tid] += red[tid + o]; __syncthreads(); }
        if (tid == 0) g_gate[n] = 1.f / (1.f + expf(-(red[0] + gate_b[n])));
        __syncthreads();
        float bs = 0.f;
        for (int idx = tid; idx < KW * EMB; idx += 256) {
            int w = idx / EMB, e = idx - w * EMB;
            bs += cvs[e] * conv_w[(w * (3 * EMB) + 2 * EMB + e) * KN + n];
        }
        red[tid] = bs; __syncthreads();
        for (int o = 128; o; o >>= 1) { if (tid < o) red[tid] += red[tid + o]; __syncthreads(); }
        if (tid == 0) g_bias[n] = red[0] + conv_b[n];
    } else {
        // fold Weff = W1 + cv[e]*W2 - W3 -> bf16 hi/lo, row n' = w*50+n
        const int total = NCHK * BN * KC;   // 81920
        for (int idx = (bid - KN) * 256 + tid; idx < total; idx += 100 * 256) {
            int k = idx & 63;
            int r = (idx >> 6) & (BN - 1);
            int c = idx >> 14;
            float v = 0.f;
            if (r < KW * KN) {
                int w = r / KN, n = r - w * KN;
                int e = c * KC + k;
                if (e < EMB) {
                    int base = w * (3 * EMB);
                    v = conv_w[(base + e) * KN + n]
                      + cvs[e] * conv_w[(base + EMB + e) * KN + n]
                      -          conv_w[(base + 2 * EMB + e) * KN + n];
                }
            }
            unsigned short hi = f2bf(v);
            unsigned short lo = f2bf(v - bf2f(hi));
            g_bimg[((c * 2 + 0) * BN + r) * KC + k] = hi;
            g_bimg[((c * 2 + 1) * BN + r) * KC + k] = lo;
        }
    }
}

// ---------------- main kernel: 1 doc/CTA, 448 thr (14 warps), double-buffered
// in-buffer offsets (bytes):
#define O_EHI  0
#define O_ELO  16128                     // 112*144
#define O_BHI  32256
#define O_BLO  69120                     // + 256*144
#define BUFSZ  105984                    // + 256*144
#define BUF0   2048
#define BUF1   (BUF0 + BUFSZ)            // 108032
#define DSM_OFF BUF1                     // Dsm aliases BUF1 (last gemm uses BUF0)
#define DSTRIDE 264
#define SMEM_BYTES (BUF1 + BUFSZ)        // 214016

__global__ __launch_bounds__(448, 1)
void dazer_main(const int* __restrict__ input_d,
                const float* __restrict__ emb,
                const float* __restrict__ hid_w,
                const float* __restrict__ hid_b,
                const float* __restrict__ score_w,
                const float* __restrict__ score_b,
                float* __restrict__ out, int Btot) {
    extern __shared__ char smc[];
    int*   docids = (int*)smc;                    // [104]
    float* enc    = (float*)(smc + 448);          // [152]
    float* mlp1s  = (float*)(smc + 1088);         // [76]
    float* Dsm    = (float*)(smc + DSM_OFF);      // [100][264]

    const int tid  = threadIdx.x;
    const int lane = tid & 31;
    const int wid  = tid >> 5;        // 0..13
    const int mt   = wid >> 1;        // 0..6
    const int nh   = wid & 1;         // 0..1
    const int b    = blockIdx.x;

    if (tid < SEQ) docids[tid] = input_d[b * SEQ + tid];
    __syncthreads();

    const uint32_t sb = smem_u32(smc);
    const uint32_t brow = (uint32_t)((lane & 7) + ((lane & 16) >> 1));

    // ---- staging lambdas ----
    float2 ev[8];                                  // E values in flight
    auto stageE_load = [&](int c) {
        #pragma unroll
        for (int i = 0; i < 8; i++) {
            int idx = i * 448 + tid;               // 3584 = 112 rows * 32 kp
            float2 v = make_float2(0.f, 0.f);
            if (idx < MROWS * 32) {
                int row = idx >> 5, kp = idx & 31;
                int e0  = c * KC + kp * 2;
                if (row < SEQ) {
                    const float* er = emb + (size_t)docids[row] * EMB;
                    if (e0 < EMB)     v.x = er[e0];
                    if (e0 + 1 < EMB) v.y = er[e0 + 1];
                }
            }
            ev[i] = v;
        }
    };
    auto stageE_store = [&](int base) {
        #pragma unroll
        for (int i = 0; i < 8; i++) {
            int idx = i * 448 + tid;
            if (idx < MROWS * 32) {
                int row = idx >> 5, kp = idx & 31;
                unsigned short h0 = f2bf(ev[i].x), h1 = f2bf(ev[i].y);
                unsigned short l0 = f2bf(ev[i].x - bf2f(h0));
                unsigned short l1 = f2bf(ev[i].y - bf2f(h1));
                *(uint32_t*)(smc + base + O_EHI + row * 144 + kp * 4) =
                    (uint32_t)h0 | ((uint32_t)h1 << 16);
                *(uint32_t*)(smc + base + O_ELO + row * 144 + kp * 4) =
                    (uint32_t)l0 | ((uint32_t)l1 << 16);
            }
        }
    };
    auto stageB = [&](int c, int base) {           // async, no registers held
        const char* bsrc = (const char*)g_bimg;
        #pragma unroll
        for (int img = 0; img < 2; img++) {
            int dsto = base + (img ? O_BLO : O_BHI);
            #pragma unroll
            for (int i = 0; i < 5; i++) {          // 2048 per img / 448 thr
                int idx = i * 448 + tid;
                if (idx < BN * 8) {
                    int row = idx >> 3, u = idx & 7;
                    uint32_t dst = sb + (uint32_t)(dsto + row * 144 + u * 16);
                    const void* src = bsrc +
                        ((size_t)((c * 2 + img) * BN + row) * KC) * 2 + u * 16;
                    asm volatile("cp.async.cg.shared.global [%0], [%1], 16;"
                                 :: "r"(dst), "l"(src));
                }
            }
        }
        asm volatile("cp.async.commit_group;" ::: "memory");
    };

    // ---- prologue: chunk 0 into BUF0 ----
    stageB(0, BUF0);
    stageE_load(0);
    stageE_store(BUF0);
    asm volatile("cp.async.wait_group 0;" ::: "memory");
    __syncthreads();

    float acc[64];
    #pragma unroll
    for (int i = 0; i < 64; i++) acc[i] = 0.f;

    #pragma unroll 1
    for (int c = 0; c < NCHK; c++) {
        const int eb = (c & 1) ? BUF1 : BUF0;
        const int ob = (c & 1) ? BUF0 : BUF1;
        if (c + 1 < NCHK) {
            stageB(c + 1, ob);                     // async into other buffer
            stageE_load(c + 1);                    // LDG latency hidden by gemm
        }

        // ---- warp GEMM: D[16,128] += E[16,64] * B[128,64]^T, 3 split terms
        const uint32_t aH = sb + (uint32_t)(eb + O_EHI
                          + (mt * 16 + (lane & 15)) * 144 + ((lane >> 4) * 16));
        const uint32_t aL = aH + (O_ELO - O_EHI);
        const uint32_t bH = sb + (uint32_t)(eb + O_BHI
                          + (nh * 128 + brow) * 144 + ((lane & 8) << 1));
        const uint32_t bL = bH + (O_BLO - O_BHI);
        const int ksmax = (c == NCHK - 1) ? 3 : 4; // K-trim: e>=304 all zero
        #pragma unroll
        for (int ks = 0; ks < 4; ks++) {
            if (ks >= ksmax) break;
            uint32_t ah[4], al[4];
            ldsm_x4(ah, aH + ks * 32);
            ldsm_x4(al, aL + ks * 32);
            #pragma unroll
            for (int jp = 0; jp < 8; jp++) {
                uint32_t bb = (uint32_t)(jp * 16 * 144 + ks * 32);
                uint32_t bh[4], bl[4];
                ldsm_x4(bh, bH + bb);
                mma_bf16(acc + (2 * jp) * 4,     ah, bh);
                mma_bf16(acc + (2 * jp + 1) * 4, ah, bh + 2);
                mma_bf16(acc + (2 * jp) * 4,     al, bh);
                mma_bf16(acc + (2 * jp + 1) * 4, al, bh + 2);
                ldsm_x4(bl, bL + bb);
                mma_bf16(acc + (2 * jp) * 4,     ah, bl);
                mma_bf16(acc + (2 * jp + 1) * 4, ah, bl + 2);
            }
        }

        if (c + 1 < NCHK) {
            stageE_store(ob);
            asm volatile("cp.async.wait_group 0;" ::: "memory");
        }
        __syncthreads();
    }

    // ---- dump fragments to Dsm (aliases BUF1; last gemm used BUF0) ----
    {
        int r0 = mt * 16 + (lane >> 2);
        int cb = (lane & 3) * 2;
        #pragma unroll
        for (int j = 0; j < 16; j++) {
            int col = nh * 128 + j * 8 + cb;
            if (r0 < SEQ) {
                Dsm[r0 * DSTRIDE + col]     = acc[j * 4 + 0];
                Dsm[r0 * DSTRIDE + col + 1] = acc[j * 4 + 1];
            }
            if (r0 + 8 < SEQ) {
                Dsm[(r0 + 8) * DSTRIDE + col]     = acc[j * 4 + 2];
                Dsm[(r0 + 8) * DSTRIDE + col + 1] = acc[j * 4 + 3];
            }
        }
    }
    __syncthreads();

    // ---- top-3 per filter with on-the-fly conv (w ascending, == R14) ----
    if (tid < KN) {
        const int n = tid;
        const float gg = g_gate[n], bb = g_bias[n];
        float v1 = -1e30f, v2 = -1e30f, v3 = -1e30f;
        int   i1 = 0, i2 = 0, i3 = 0;
        for (int t = 0; t < LP; t++) {
            float s = 0.f;
            #pragma unroll
            for (int w = 0; w < KW; w++) s += Dsm[(t + w) * DSTRIDE + w * KN + n];
            float v = gg * (s + bb);
            if (v > v1)      { v3 = v2; i3 = i2; v2 = v1; i2 = i1; v1 = v; i1 = t; }
            else if (v > v2) { v3 = v2; i3 = i2; v2 = v;  i2 = t; }
            else if (v > v3) { v3 = v;  i3 = t; }
        }
        float va = v1, vb = v2, vc = v3; int ia = i1, ib = i2, ic = i3;
        if (ia > ib) { float tv = va; va = vb; vb = tv; int ti = ia; ia = ib; ib = ti; }
        if (ib > ic) { float tv = vb; vb = vc; vc = tv; int ti = ib; ib = ic; ic = ti; }
        if (ia > ib) { float tv = va; va = vb; vb = tv; int ti = ia; ia = ib; ib = ti; }
        enc[n * 3 + 0] = va; enc[n * 3 + 1] = vb; enc[n * 3 + 2] = vc;
    }
    __syncthreads();

    // ---- mlp1 = tanh(enc @ hid_w + hid_b) ----
    if (tid < MLP1) {
        float s = hid_b[tid];
        #pragma unroll 5
        for (int i = 0; i < KN * KMAX; i++) s += enc[i] * hid_w[i * MLP1 + tid];
        float m = tanhf(s);
        mlp1s[tid] = m;
        out[(size_t)b * MLP1 + tid] = m;
    }
    __syncthreads();

    // ---- score ----
    if (tid == 0) {
        float s = score_b[0];
        for (int j = 0; j < MLP1; j++) s += mlp1s[j] * score_w[j];
        out[(size_t)Btot * MLP1 + b] = tanhf(s);
    }
}

// ---------------- launch ----------------
extern "C" void kernel_launch(void* const* d_in, const int* in_sizes, int n_in,
                              void* d_out, int out_size) {
    const int*   input_q   = (const int*)  d_in[0];
    const int*   input_d   = (const int*)  d_in[1];
    const float* emb_table = (const float*)d_in[2];
    const float* conv_w    = (const float*)d_in[3];
    const float* conv_b    = (const float*)d_in[4];
    const float* gate_w    = (const float*)d_in[5];
    const float* gate_b    = (const float*)d_in[6];
    const float* hid_w     = (const float*)d_in[7];
    const float* hid_b     = (const float*)d_in[8];
    const float* score_w   = (const float*)d_in[9];
    const float* score_b   = (const float*)d_in[10];
    float* out = (float*)d_out;

    const int Btot = in_sizes[1] / SEQ;   // 2048

    cudaFuncSetAttribute(dazer_main, cudaFuncAttributeMaxDynamicSharedMemorySize, SMEM_BYTES);

    dazer_prepA<<<1, 320>>>(input_q, emb_table);
    dazer_prepB<<<150, 256>>>(conv_w, conv_b, gate_w, gate_b);
    dazer_main<<<Btot, 448, SMEM_BYTES>>>(input_d, emb_table, hid_w, hid_b,
                                          score_w, score_b, out, Btot);
}